// round 11
// baseline (speedup 1.0000x reference)
#include <cuda_runtime.h>
#include <cuda_fp16.h>

// Problem constants
#define HID     50
#define NG      200
#define IN0     17
#define SDIM    16
#define TSTEPS  128
#define FC1N    25

// Tiling: two independent 32-row halves, 13 warps each (R10 structure)
#define ROWS      64
#define HROWS     32
#define NTHREADS  832
#define HTHREADS  416

// Strides
#define FC1_S     51
#define TSTRIDE   68      // floats; 272B rows, 16B-aligned
#define W2I_S     17      // wih0 half4-unit stride per j (8B units)
#define W2H_S     51      // hh half4-unit stride per j; 51*2=102 words -> 6j mod 32 all-distinct

typedef unsigned long long ull;

__device__ __forceinline__ ull pack2(float a, float b) {
    ull r; asm("mov.b64 %0,{%1,%2};" : "=l"(r) : "f"(a), "f"(b)); return r;
}
__device__ __forceinline__ float2 unpk(ull v) {
    float2 f; asm("mov.b64 {%0,%1},%2;" : "=f"(f.x), "=f"(f.y) : "l"(v)); return f;
}
__device__ __forceinline__ void fma2(ull& d, ull a, ull b) {
    asm("fma.rn.f32x2 %0,%1,%2,%0;" : "+l"(d) : "l"(a), "l"(b));
}
__device__ __forceinline__ void add2(ull& d, ull a) {
    asm("add.rn.f32x2 %0,%0,%1;" : "+l"(d) : "l"(a));
}
__device__ __forceinline__ float tanh_a(float x) {
    float y; asm("tanh.approx.f32 %0,%1;" : "=f"(y) : "f"(x)); return y;
}
__device__ __forceinline__ float sig_a(float x) {
    return fmaf(tanh_a(0.5f * x), 0.5f, 0.5f);
}
__device__ __forceinline__ void half_bar(int half) {
    asm volatile("bar.sync %0, %1;" :: "r"(half + 1), "r"(HTHREADS) : "memory");
}

// Shared layout (float offsets)
#define OFF_W2_IH0 0         // 50*17*4 halves = 1700 floats
#define OFF_W2_HH0 1700      // 50*51*4 halves = 5100 floats
#define OFF_W2_IH1 6800      // 5100
#define OFF_W2_HH1 11900     // 5100
#define OFF_FC1    17000     // 1275
#define OFF_FC2    18276     // 25
#define OFF_B0     18302     // 200
#define OFF_B1     18502     // 200
#define OFF_BFC1   18702     // 25
#define OFF_BFC2   18728     // 2 (+2 pad)
#define OFF_X      18732     // 17*68 = 1156  (16B aligned: 18732*4 % 16 == 0)
#define OFF_H0     19888     // 2*50*68 = 6800
#define OFF_H1     26688     // 6800
#define SMEM_FLOATS 33488    // 133952 bytes

// One k of gate MACs: half4 weights (4 gates, 8B), one LDS.128 of state (4 rows)
#define GATEKH(PW, SBASE, K) do { \
    ull wq_ = (PW)[K]; \
    uint2 wu_; asm("mov.b64 {%0,%1},%2;" : "=r"(wu_.x), "=r"(wu_.y) : "l"(wq_)); \
    float2 wa_ = __half22float2(*(__half2*)&wu_.x);  /* (wi, wf) */ \
    float2 wb_ = __half22float2(*(__half2*)&wu_.y);  /* (wg, wo) */ \
    ull wi_ = pack2(wa_.x, wa_.x), wf_ = pack2(wa_.y, wa_.y); \
    ull wg_ = pack2(wb_.x, wb_.x), wo_ = pack2(wb_.y, wb_.y); \
    ulonglong2 sv_ = *(const ulonglong2*)((SBASE) + (K) * TSTRIDE); \
    fma2(ai[0], wi_, sv_.x); fma2(ai[1], wi_, sv_.y); \
    fma2(af[0], wf_, sv_.x); fma2(af[1], wf_, sv_.y); \
    fma2(ag[0], wg_, sv_.x); fma2(ag[1], wg_, sv_.y); \
    fma2(ao[0], wo_, sv_.x); fma2(ao[1], wo_, sv_.y); \
} while (0)

// LSTM nonlinearity for this thread's 4 rows (2 f32x2 pairs); no gate exchange needed
#define EPILOGUE(LYR, HDST) do { \
    float hv_[4]; \
    _Pragma("unroll") \
    for (int p = 0; p < 2; p++) { \
        float2 vi_ = unpk(ai[p]), vf_ = unpk(af[p]); \
        float2 vg_ = unpk(ag[p]), vo_ = unpk(ao[p]); \
        float ncx_ = sig_a(vf_.x) * cx[LYR][p] + sig_a(vi_.x) * tanh_a(vg_.x); \
        float ncy_ = sig_a(vf_.y) * cy[LYR][p] + sig_a(vi_.y) * tanh_a(vg_.y); \
        cx[LYR][p] = ncx_; cy[LYR][p] = ncy_; \
        hv_[2*p]     = sig_a(vo_.x) * tanh_a(ncx_); \
        hv_[2*p + 1] = sig_a(vo_.y) * tanh_a(ncy_); \
    } \
    if (!dup) { \
        float4 q_; q_.x = hv_[0]; q_.y = hv_[1]; q_.z = hv_[2]; q_.w = hv_[3]; \
        *(float4*)&(HDST)[j * TSTRIDE + r0] = q_; \
    } \
} while (0)

__global__ __launch_bounds__(NTHREADS, 1)
void kozyra_lstm_kernel(const float* __restrict__ features,
                        const float* __restrict__ w_ih0, const float* __restrict__ w_hh0,
                        const float* __restrict__ b0,
                        const float* __restrict__ w_ih1, const float* __restrict__ w_hh1,
                        const float* __restrict__ b1,
                        const float* __restrict__ w_fc1, const float* __restrict__ b_fc1,
                        const float* __restrict__ w_fc2, const float* __restrict__ b_fc2,
                        float* __restrict__ out)
{
    extern __shared__ float sm[];
    float* s_fc1  = sm + OFF_FC1;
    float* s_fc2  = sm + OFF_FC2;
    float* s_b0   = sm + OFF_B0;
    float* s_b1   = sm + OFF_B1;
    float* s_bfc1 = sm + OFF_BFC1;
    float* s_bfc2 = sm + OFF_BFC2;
    float* s_x    = sm + OFF_X;      // [IN0][TSTRIDE], row 16 = delta
    float* s_h0b  = sm + OFF_H0;     // 2 x [HID][TSTRIDE]
    float* s_h1b  = sm + OFF_H1;

    const int tid  = threadIdx.x;
    const int brow = blockIdx.x * ROWS;

    // ---- Stage weights as fp16, interleaved half4 (wi,wf,wg,wo) per (j,k) ----
    {
        __half* hwih0 = (__half*)(sm + OFF_W2_IH0);
        for (int i = tid; i < HID * IN0 * 4; i += NTHREADS) {
            int gate = i & 3, rest = i >> 2;
            int j = rest / IN0, k = rest % IN0;
            hwih0[(j * W2I_S + k) * 4 + gate] = __float2half_rn(w_ih0[(gate * HID + j) * IN0 + k]);
        }
        __half* hhh0 = (__half*)(sm + OFF_W2_HH0);
        __half* hih1 = (__half*)(sm + OFF_W2_IH1);
        __half* hhh1 = (__half*)(sm + OFF_W2_HH1);
        for (int i = tid; i < HID * W2H_S * 4; i += NTHREADS) {
            int gate = i & 3, rest = i >> 2;
            int j = rest / W2H_S, k = rest % W2H_S;
            float v0 = 0.0f, v1 = 0.0f, v2 = 0.0f;
            if (k < HID) {
                int src = (gate * HID + j) * HID + k;
                v0 = w_hh0[src]; v1 = w_ih1[src]; v2 = w_hh1[src];
            }
            int o = (j * W2H_S + k) * 4 + gate;
            hhh0[o] = __float2half_rn(v0);
            hih1[o] = __float2half_rn(v1);
            hhh1[o] = __float2half_rn(v2);
        }
    }
    for (int i = tid; i < FC1N * HID; i += NTHREADS) {
        int n = i / HID, k = i % HID;
        s_fc1[n * FC1_S + k] = w_fc1[i];
    }
    for (int i = tid; i < FC1N; i += NTHREADS) { s_fc2[i] = w_fc2[i]; s_bfc1[i] = b_fc1[i]; }
    for (int i = tid; i < NG;   i += NTHREADS) { s_b0[i] = b0[i]; s_b1[i] = b1[i]; }
    if (tid == 0) s_bfc2[0] = b_fc2[0];

    // ---- Init state + x for t=0 ----
    for (int i = tid; i < 2 * HID * TSTRIDE; i += NTHREADS) { s_h0b[i] = 0.0f; s_h1b[i] = 0.0f; }
    const float* fbase = features + (size_t)brow * (TSTEPS * SDIM);
    for (int i = tid; i < ROWS * SDIM; i += NTHREADS) {
        int r = i >> 4, s = i & 15;
        s_x[s * TSTRIDE + r] = fbase[(size_t)r * (TSTEPS * SDIM) + s];
    }
    if (tid < ROWS) s_x[SDIM * TSTRIDE + tid] = 0.0f;
    __syncthreads();   // last full-block barrier

    // ---- Thread mapping: half (13 warps, 32 rows); gs selects a 4-row subgroup ----
    const int w    = tid >> 5;
    const int lane = tid & 31;
    const int half = (w >= 13) ? 1 : 0;
    const int hw   = w - half * 13;
    const int gs   = lane >> 4;
    const int sub  = lane & 15;
    int rg, j; bool dup = false;
    if (hw < 12) { rg = hw / 3; j = (hw % 3) * 16 + sub; }
    else { j = 48 + (sub & 1); rg = (sub >> 1) & 3; dup = (sub >= 8); }
    const int hbase = half * HROWS;
    const int r0 = hbase + rg * 8 + gs * 4;   // this thread's 4 rows

    const ull* pW_ih0 = (const ull*)(sm + OFF_W2_IH0) + j * W2I_S;
    const ull* pW_hh0 = (const ull*)(sm + OFF_W2_HH0) + j * W2H_S;
    const ull* pW_ih1 = (const ull*)(sm + OFF_W2_IH1) + j * W2H_S;
    const ull* pW_hh1 = (const ull*)(sm + OFF_W2_HH1) + j * W2H_S;

    // Bias packs (all 4 gates, both layers) — fp32
    const ull bi0 = pack2(s_b0[j], s_b0[j]);
    const ull bf0 = pack2(s_b0[HID + j], s_b0[HID + j]);
    const ull bg0 = pack2(s_b0[2*HID + j], s_b0[2*HID + j]);
    const ull bo0 = pack2(s_b0[3*HID + j], s_b0[3*HID + j]);
    const ull bi1 = pack2(s_b1[j], s_b1[j]);
    const ull bf1 = pack2(s_b1[HID + j], s_b1[HID + j]);
    const ull bg1 = pack2(s_b1[2*HID + j], s_b1[2*HID + j]);
    const ull bo1 = pack2(s_b1[3*HID + j], s_b1[3*HID + j]);

    float cx[2][2], cy[2][2];
    cx[0][0]=cx[0][1]=cy[0][0]=cy[0][1]=0.0f;
    cx[1][0]=cx[1][1]=cy[1][0]=cy[1][1]=0.0f;

    for (int t = 0; t < TSTEPS; t++) {
        const int pb = t & 1;
        float* h0r = s_h0b + pb * (HID * TSTRIDE);
        float* h0w = s_h0b + (pb ^ 1) * (HID * TSTRIDE);
        float* h1r = s_h1b + pb * (HID * TSTRIDE);
        float* h1w = s_h1b + (pb ^ 1) * (HID * TSTRIDE);

        ull ai[2], af[2], ag[2], ao[2];

        // ================= Layer 0 =================
        ai[0]=ai[1]=bi0; af[0]=af[1]=bf0; ag[0]=ag[1]=bg0; ao[0]=ao[1]=bo0;
        {
            const float* sx = &s_x[r0];
            #pragma unroll
            for (int k = 0; k < IN0; k++) GATEKH(pW_ih0, sx, k);
        }
        {
            const float* sh = &h0r[r0];
            #pragma unroll 5
            for (int k = 0; k < HID; k++) GATEKH(pW_hh0, sh, k);
        }
        EPILOGUE(0, h0w);
        half_bar(half);   // h0 rows of this half visible

        // ================= Layer 1 =================
        ai[0]=ai[1]=bi1; af[0]=af[1]=bf1; ag[0]=ag[1]=bg1; ao[0]=ao[1]=bo1;
        {
            const float* sh = &h0w[r0];
            #pragma unroll 5
            for (int k = 0; k < HID; k++) GATEKH(pW_ih1, sh, k);
        }
        {
            const float* sh = &h1r[r0];
            #pragma unroll 5
            for (int k = 0; k < HID; k++) GATEKH(pW_hh1, sh, k);
        }
        EPILOGUE(1, h1w);
        half_bar(half);   // h1 rows of this half visible

        // ========= fc1+fc2 fused (4 rows per warp, warps 0-7) + x for t+1 =========
        const bool has_next = (t + 1 < TSTEPS);
        // feature prefetch for this half's 32 rows (512 elems / 416 threads)
        int hidx = hw * 32 + lane;
        float f0 = 0.0f, f1 = 0.0f;
        int rA = hidx >> 4, sA = hidx & 15;
        int hidx2 = hidx + HTHREADS;
        int rB = hidx2 >> 4, sB = hidx2 & 15;
        if (has_next) {
            f0 = fbase[(size_t)(hbase + rA) * (TSTEPS * SDIM) + (size_t)(t + 1) * SDIM + sA];
            if (rB < HROWS)
                f1 = fbase[(size_t)(hbase + rB) * (TSTEPS * SDIM) + (size_t)(t + 1) * SDIM + sB];
        }

        if (hw < 8) {
            int rb = hbase + hw * 4;
            ull acc0 = 0ULL, acc1 = 0ULL;
            if (lane < FC1N) {
                float bb1 = s_bfc1[lane];
                acc0 = pack2(bb1, bb1); acc1 = acc0;
                const float* wr = &s_fc1[lane * FC1_S];
                #pragma unroll 10
                for (int k = 0; k < HID; k++) {
                    float wv = wr[k];
                    ull wp = pack2(wv, wv);
                    ulonglong2 hv = *(const ulonglong2*)&h1w[k * TSTRIDE + rb];
                    fma2(acc0, wp, hv.x);
                    fma2(acc1, wp, hv.y);
                }
                float2 u0 = unpk(acc0), u1 = unpk(acc1);
                float sc = s_fc2[lane];
                u0.x = fmaxf(u0.x, 0.0f) * sc;  u0.y = fmaxf(u0.y, 0.0f) * sc;
                u1.x = fmaxf(u1.x, 0.0f) * sc;  u1.y = fmaxf(u1.y, 0.0f) * sc;
                acc0 = pack2(u0.x, u0.y); acc1 = pack2(u1.x, u1.y);
            }
            #pragma unroll
            for (int off = 16; off > 0; off >>= 1) {
                add2(acc0, __shfl_down_sync(0xffffffffu, acc0, off));
                add2(acc1, __shfl_down_sync(0xffffffffu, acc1, off));
            }
            if (lane == 0) {
                float2 d0 = unpk(acc0), d1 = unpk(acc1);
                float bb = s_bfc2[0];
                d0.x += bb; d0.y += bb; d1.x += bb; d1.y += bb;
                float4 dd; dd.x = d0.x; dd.y = d0.y; dd.z = d1.x; dd.w = d1.y;
                *(float4*)&s_x[SDIM * TSTRIDE + rb] = dd;   // delta -> next x
                out[(size_t)(brow + rb)     * TSTEPS + t] = d0.x;
                out[(size_t)(brow + rb + 1) * TSTEPS + t] = d0.y;
                out[(size_t)(brow + rb + 2) * TSTEPS + t] = d1.x;
                out[(size_t)(brow + rb + 3) * TSTEPS + t] = d1.y;
            }
        }

        // store prefetched features for t+1 (this half's rows)
        if (has_next) {
            s_x[sA * TSTRIDE + hbase + rA] = f0;
            if (rB < HROWS)
                s_x[sB * TSTRIDE + hbase + rB] = f1;
        }
        half_bar(half);   // delta + x(t+1) visible within half
    }
}

extern "C" void kernel_launch(void* const* d_in, const int* in_sizes, int n_in,
                              void* d_out, int out_size)
{
    const float* features = (const float*)d_in[0];
    const float* w_ih0    = (const float*)d_in[1];
    const float* w_hh0    = (const float*)d_in[2];
    const float* b0       = (const float*)d_in[3];
    const float* w_ih1    = (const float*)d_in[4];
    const float* w_hh1    = (const float*)d_in[5];
    const float* b1       = (const float*)d_in[6];
    const float* w_fc1    = (const float*)d_in[7];
    const float* b_fc1    = (const float*)d_in[8];
    const float* w_fc2    = (const float*)d_in[9];
    const float* b_fc2    = (const float*)d_in[10];
    float* out = (float*)d_out;

    const int batch = in_sizes[0] / (TSTEPS * SDIM);
    const int nblocks = batch / ROWS;

    const size_t smem_bytes = SMEM_FLOATS * sizeof(float);
    cudaFuncSetAttribute(kozyra_lstm_kernel,
                         cudaFuncAttributeMaxDynamicSharedMemorySize,
                         (int)smem_bytes);

    kozyra_lstm_kernel<<<nblocks, NTHREADS, smem_bytes>>>(
        features, w_ih0, w_hh0, b0, w_ih1, w_hh1, b1,
        w_fc1, b_fc1, w_fc2, b_fc2, out);
}